// round 14
// baseline (speedup 1.0000x reference)
#include <cuda_runtime.h>
#include <cuda_fp16.h>
#include <cstdint>

// ---------------- problem constants ----------------
#define EDGES   262144
#define NNODES  32768
#define DD      128
#define FFH     512
#define LAYERS  2
#define KCAT    384

#define WT_PER_LAYER 294912

// ---------------- scratch ----------------
__device__ float  g_edge [EDGES * DD];     // fp32 edge (residual/LN)
__device__ float  g_agg  [NNODES * DD];
__device__ float  g_ideg [NNODES];
__device__ __half g_wt   [LAYERS * WT_PER_LAYER];
__device__ __half g_nodesh[NNODES * DD];   // fp16 k-permuted mirror of nodes
__device__ __half g_edgeh [EDGES * DD];    // fp16 k-permuted mirror of edge
__device__ __half g_ffh  [NNODES * FFH];   // fp16 k-permuted FF hidden

enum { EPI_RELU = 0, EPI_ATOMIC = 1, EPI_LNRES = 2 };

#define TPITCH_H 48            // halves per tile row (96 B)
#define HROW_H   208           // halves per HA row (4 chunks * 48 + pad)
static const int TILE_BYTES = 128 * TPITCH_H * 2;   // 12288
static const int HA_BYTES   = 128 * HROW_H * 2;     // 53248
static const int STAGE_B    = 128 * 132 * 4;        // 67584
static const int DYN_MLP    = HA_BYTES + 2 * TILE_BYTES + 1024;   // 78848
static const int DYN_GEMM   = STAGE_B + 1024;                     // 68608

// ---------------- device helpers ----------------
__device__ __forceinline__ void mma16(float* d, uint32_t a0, uint32_t a1,
                                      uint32_t a2, uint32_t a3,
                                      uint32_t b0, uint32_t b1) {
    asm volatile(
        "mma.sync.aligned.m16n8k16.row.col.f32.f16.f16.f32 "
        "{%0,%1,%2,%3}, {%4,%5,%6,%7}, {%8,%9}, {%0,%1,%2,%3};"
        : "+f"(d[0]), "+f"(d[1]), "+f"(d[2]), "+f"(d[3])
        : "r"(a0), "r"(a1), "r"(a2), "r"(a3), "r"(b0), "r"(b1));
}
template <int MT>
__device__ __forceinline__ void chunk_f16(const __half* A, int apitch,
                                          const __half* B,
                                          int wm, int wn, int g, int r,
                                          float acc[][8][4]) {
#pragma unroll
    for (int s = 0; s < 2; s++) {
        uint2 alo[MT], ahi[MT];
#pragma unroll
        for (int mt = 0; mt < MT; mt++) {
            const __half* p0 = A + (wm + mt * 16 + g) * apitch + s * 16 + r * 4;
            alo[mt] = *(const uint2*)p0;
            ahi[mt] = *(const uint2*)(p0 + 8 * apitch);
        }
        uint2 bf[8];
#pragma unroll
        for (int nt = 0; nt < 8; nt++)
            bf[nt] = *(const uint2*)(B + (wn + nt * 8 + g) * TPITCH_H + s * 16 + r * 4);
#pragma unroll
        for (int mt = 0; mt < MT; mt++)
#pragma unroll
            for (int nt = 0; nt < 8; nt++)
                mma16(acc[mt][nt], alo[mt].x, ahi[mt].x, alo[mt].y, ahi[mt].y,
                      bf[nt].x, bf[nt].y);
    }
}
// k-within-16 for permuted position p (0..15)
__device__ __forceinline__ int uperm(int p) {
    int rr = p >> 2, qq = p & 3;
    return (qq & 1) | (rr << 1) | ((qq >> 1) << 3);
}
// write float4 (4 consecutive k at group c4 of a 32-k block) permuted as fp16
__device__ __forceinline__ void put4(__half* blk, int c4, float4 v) {
    int s  = c4 >> 2, jm = c4 & 3;
    int p1 = ((jm & 1) << 3) | ((jm >> 1) << 1);      // 0,8,2,10
    __half* b = blk + s * 16 + p1;
    *(__half2*)b       = __floats2half2_rn(v.x, v.y);
    *(__half2*)(b + 4) = __floats2half2_rn(v.z, v.w);
}
// stage (fp32, pitch 132, 128x128 tile) -> permuted fp16 global, coalesced.
// If bias != nullptr: v = relu(v + bias[n0 + k]).
__device__ __forceinline__ void mirror_stage(const float* stage,
                                             __half* dsth, int ldo_h, int n0_h,
                                             const float* bias, int tid) {
    for (int i = tid; i < 2048; i += 256) {
        int row = i >> 4;
        int w   = i & 15;
        int c = w >> 2, ww = w & 3;
        int s = ww >> 1, h8 = ww & 1;
        const float* srow = stage + row * 132 + c * 32 + s * 16;
        int kbase = n0_h + c * 32 + s * 16;
        uint32_t pk[4];
#pragma unroll
        for (int t2 = 0; t2 < 4; t2++) {
            int p0 = h8 * 8 + t2 * 2;
            int u0 = uperm(p0), u1 = uperm(p0 + 1);
            float v0 = srow[u0], v1 = srow[u1];
            if (bias) {
                v0 = fmaxf(v0 + __ldg(bias + kbase + u0), 0.f);
                v1 = fmaxf(v1 + __ldg(bias + kbase + u1), 0.f);
            }
            __half2 hh = __floats2half2_rn(v0, v1);
            pk[t2] = *(uint32_t*)&hh;
        }
        *(uint4*)(dsth + (size_t)row * ldo_h + n0_h + c * 32 + s * 16 + h8 * 8) =
            make_uint4(pk[0], pk[1], pk[2], pk[3]);
    }
}

// ------- fused 3-linear MLP over edges (fp16 mirrors, 8 warps x 32x64) -----
template <int EPI>
__global__ void __launch_bounds__(256, 2)
mlp3_tc(const __half* __restrict__ nodesh, const __half* __restrict__ edgeh,
        const int* __restrict__ srcI, const int* __restrict__ dstI,
        const __half* __restrict__ W0t, const float* __restrict__ b0,
        const __half* __restrict__ W1t, const float* __restrict__ b1,
        const __half* __restrict__ W2t, const float* __restrict__ b2,
        float* __restrict__ out, __half* __restrict__ outh,
        const float* __restrict__ resid,
        const float* __restrict__ lng, const float* __restrict__ lnb)
{
    extern __shared__ char dyn[];
    char*   basep = (char*)(((uintptr_t)dyn + 1023) & ~(uintptr_t)1023);
    __half* HA    = (__half*)basep;                      // [128][HROW_H]
    __half* BsA[2] = { (__half*)(basep + HA_BYTES),
                       (__half*)(basep + HA_BYTES + TILE_BYTES) };
    float*  stage = (float*)basep;                       // reuse, pitch 132

    __shared__ int s_src[128], s_dst[128];

    const int tid  = threadIdx.x;
    const int wid  = tid >> 5;
    const int lane = tid & 31;
    const int g    = lane >> 2;
    const int r    = lane & 3;
    const int wm   = (wid & 3) * 32;
    const int wn   = (wid >> 2) * 64;
    const int m0   = blockIdx.x * 128;

    if (tid < 128) { s_src[tid] = srcI[m0 + tid]; s_dst[tid] = dstI[m0 + tid]; }
    __syncthreads();

    float acc[2][8][4];
#pragma unroll
    for (int mt = 0; mt < 2; mt++)
#pragma unroll
        for (int nt = 0; nt < 8; nt++)
#pragma unroll
            for (int q = 0; q < 4; q++) acc[mt][nt][q] = 0.f;

    int arow[2], aq[2];
#pragma unroll
    for (int i = 0; i < 2; i++) {
        int v = tid + i * 256;
        arow[i] = v >> 2;
        aq[i]   = v & 3;
    }
    const int brow = tid >> 2, bv4 = tid & 3;
    const int brow2 = (tid + 256) >> 2, bv42 = (tid + 256) & 3;

    uint4 prefA[2];
    uint4 prefB[2];

    auto ldgA = [&](int c) {
        int k0 = c * 32;
#pragma unroll
        for (int i = 0; i < 2; i++) {
            const __half* ap;
            if (k0 < 128)      ap = nodesh + (size_t)s_src[arow[i]] * 128 + k0 + aq[i] * 8;
            else if (k0 < 256) ap = edgeh + (size_t)(m0 + arow[i]) * 128 + (k0 - 128) + aq[i] * 8;
            else               ap = nodesh + (size_t)s_dst[arow[i]] * 128 + (k0 - 256) + aq[i] * 8;
            prefA[i] = *(const uint4*)ap;
        }
    };
    auto stsA = [&](int c) {
        __half* slot = HA + (c & 3) * TPITCH_H;
#pragma unroll
        for (int i = 0; i < 2; i++)
            *(uint4*)(slot + arow[i] * HROW_H + aq[i] * 8) = prefA[i];
    };
    auto ldgB = [&](const __half* Wt, int Kdim, int c) {
        prefB[0] = *(const uint4*)((const char*)(Wt + (size_t)brow  * Kdim + c * 32) + bv4  * 16);
        prefB[1] = *(const uint4*)((const char*)(Wt + (size_t)brow2 * Kdim + c * 32) + bv42 * 16);
    };
    auto stsB = [&](__half* Bbuf) {
        *(uint4*)((char*)(Bbuf + brow  * TPITCH_H) + bv4  * 16) = prefB[0];
        *(uint4*)((char*)(Bbuf + brow2 * TPITCH_H) + bv42 * 16) = prefB[1];
    };
    auto wbRelu = [&](const float* bias) {
#pragma unroll
        for (int mt = 0; mt < 2; mt++)
#pragma unroll
            for (int q = 0; q < 4; q++) {
                int row = wm + mt * 16 + g + ((q & 2) ? 8 : 0);
#pragma unroll
                for (int nt = 0; nt < 8; nt++) {
                    int col = wn + nt * 8 + 2 * r + (q & 1);
                    float v = fmaxf(acc[mt][nt][q] + __ldg(bias + col), 0.f);
                    int c  = col >> 5, u = col & 31;
                    int s  = u >> 4, uu = u & 15;
                    int rr = (uu & 7) >> 1;
                    int qq = (uu & 1) | ((uu >> 3) << 1);
                    HA[row * HROW_H + c * TPITCH_H + s * 16 + rr * 4 + qq] =
                        __float2half_rn(v);
                    acc[mt][nt][q] = 0.f;
                }
            }
    };

    // ---- stage 0: K = 384, pipelined ----
    ldgA(0); ldgB(W0t, KCAT, 0);
    for (int c = 0; c < 12; c++) {
        stsA(c);
        stsB(BsA[c & 1]);
        if (c < 11) { ldgA(c + 1); ldgB(W0t, KCAT, c + 1); }
        __syncthreads();
        chunk_f16<2>(HA + (c & 3) * TPITCH_H, HROW_H, BsA[c & 1], wm, wn, g, r, acc);
    }
    __syncthreads();
    wbRelu(b0);

    // ---- stage 1: K = 128, A resident in HA ----
    ldgB(W1t, 128, 0);
    for (int c = 0; c < 4; c++) {
        stsB(BsA[c & 1]);
        if (c < 3) ldgB(W1t, 128, c + 1);
        __syncthreads();
        chunk_f16<2>(HA + c * TPITCH_H, HROW_H, BsA[c & 1], wm, wn, g, r, acc);
    }
    __syncthreads();
    wbRelu(b1);

    // ---- stage 2: K = 128 ----
    ldgB(W2t, 128, 0);
    for (int c = 0; c < 4; c++) {
        stsB(BsA[c & 1]);
        if (c < 3) ldgB(W2t, 128, c + 1);
        __syncthreads();
        chunk_f16<2>(HA + c * TPITCH_H, HROW_H, BsA[c & 1], wm, wn, g, r, acc);
    }
    __syncthreads();

    // ---- epilogue (fp32 stage, pitch 132) ----
    if (EPI == EPI_ATOMIC) {
#pragma unroll
        for (int mt = 0; mt < 2; mt++)
#pragma unroll
            for (int q = 0; q < 4; q++) {
                int row = wm + mt * 16 + g + ((q & 2) ? 8 : 0);
#pragma unroll
                for (int nt = 0; nt < 8; nt++) {
                    int col = wn + nt * 8 + 2 * r + (q & 1);
                    stage[row * 132 + col] = acc[mt][nt][q] + __ldg(b2 + col);
                }
            }
        __syncthreads();
#pragma unroll
        for (int it = 0; it < 16; it++) {
            int f4  = it * 256 + tid;
            int row = f4 >> 5;
            int c4  = f4 & 31;
            float4 v = *(float4*)(stage + row * 132 + c4 * 4);
            float* dbase = out + (size_t)s_dst[row] * 128 + c4 * 4;
            asm volatile("red.global.add.v4.f32 [%0], {%1,%2,%3,%4};"
                         :: "l"(dbase), "f"(v.x), "f"(v.y), "f"(v.z), "f"(v.w)
                         : "memory");
        }
    } else {  // EPI_LNRES: out = LN(resid + acc + b2); fp16 mirror coalesced
#pragma unroll
        for (int mt = 0; mt < 2; mt++)
#pragma unroll
            for (int q = 0; q < 4; q++) {
                int row = wm + mt * 16 + g + ((q & 2) ? 8 : 0);
#pragma unroll
                for (int nt = 0; nt < 8; nt++) {
                    int col = wn + nt * 8 + 2 * r + (q & 1);
                    stage[row * 132 + col] = acc[mt][nt][q];
                }
            }
        __syncthreads();
        float4 gg  = *(const float4*)(lng + lane * 4);
        float4 bbn = *(const float4*)(lnb + lane * 4);
        float4 bz  = *(const float4*)(b2 + lane * 4);
        for (int rr = wid; rr < 128; rr += 8) {
            float4 res = *(const float4*)(resid + (size_t)(m0 + rr) * 128 + lane * 4);
            float4 d   = *(float4*)(stage + rr * 132 + lane * 4);
            float v0 = res.x + d.x + bz.x, v1 = res.y + d.y + bz.y;
            float v2 = res.z + d.z + bz.z, v3 = res.w + d.w + bz.w;
            float sum = v0 + v1 + v2 + v3;
#pragma unroll
            for (int off = 16; off > 0; off >>= 1)
                sum += __shfl_xor_sync(0xffffffffu, sum, off);
            float mean = sum * (1.0f / 128.0f);
            float d0 = v0 - mean, d1 = v1 - mean, d2 = v2 - mean, d3 = v3 - mean;
            float sq = d0 * d0 + d1 * d1 + d2 * d2 + d3 * d3;
#pragma unroll
            for (int off = 16; off > 0; off >>= 1)
                sq += __shfl_xor_sync(0xffffffffu, sq, off);
            float inv = rsqrtf(sq * (1.0f / 128.0f) + 1e-5f);
            float4 o;
            o.x = d0 * inv * gg.x + bbn.x;
            o.y = d1 * inv * gg.y + bbn.y;
            o.z = d2 * inv * gg.z + bbn.z;
            o.w = d3 * inv * gg.w + bbn.w;
            *(float4*)(out + (size_t)(m0 + rr) * 128 + lane * 4) = o;
            *(float4*)(stage + rr * 132 + lane * 4) = o;   // final values back
        }
        __syncthreads();
        mirror_stage(stage, outh + (size_t)m0 * 128, 128, 0, nullptr, tid);
    }
}

// ---------------- dense GEMM: A from fp16-permuted mirror ----------------
template <int EPI>
__global__ void __launch_bounds__(256, 2)
gemm_tc(const __half* __restrict__ A, int lda, int K,
        const __half* __restrict__ Wt, const float* __restrict__ bias,
        float* __restrict__ out, __half* __restrict__ outh, int ldo,
        const float* __restrict__ resid,
        const float* __restrict__ lng, const float* __restrict__ lnb)
{
    extern __shared__ char dyn[];
    char*   base  = (char*)(((uintptr_t)dyn + 1023) & ~(uintptr_t)1023);
    __half* AsA[2] = { (__half*)base, (__half*)(base + TILE_BYTES) };
    __half* BsA[2] = { (__half*)(base + 2 * TILE_BYTES),
                       (__half*)(base + 3 * TILE_BYTES) };
    float*  stage = (float*)base;

    const int tid  = threadIdx.x;
    const int wid  = tid >> 5;
    const int lane = tid & 31;
    const int g    = lane >> 2;
    const int r    = lane & 3;
    const int wm   = (wid & 3) * 32;
    const int wn   = (wid >> 2) * 64;
    const int m0   = blockIdx.x * 128;
    const int n0   = blockIdx.y * 128;

    float acc[2][8][4];
#pragma unroll
    for (int mt = 0; mt < 2; mt++)
#pragma unroll
        for (int nt = 0; nt < 8; nt++)
#pragma unroll
            for (int q = 0; q < 4; q++) acc[mt][nt][q] = 0.f;

    int arow[2], aq[2];
#pragma unroll
    for (int i = 0; i < 2; i++) {
        int v = tid + i * 256;
        arow[i] = v >> 2;
        aq[i]   = v & 3;
    }
    const int brow = tid >> 2, bv4 = tid & 3;
    const int brow2 = (tid + 256) >> 2, bv42 = (tid + 256) & 3;

    uint4 prefA[2];
    uint4 prefB[2];

    auto ldgA = [&](int c) {
#pragma unroll
        for (int i = 0; i < 2; i++)
            prefA[i] = *(const uint4*)(A + (size_t)(m0 + arow[i]) * lda + c * 32 + aq[i] * 8);
    };
    auto stsA = [&](__half* Abuf) {
#pragma unroll
        for (int i = 0; i < 2; i++)
            *(uint4*)(Abuf + arow[i] * TPITCH_H + aq[i] * 8) = prefA[i];
    };
    auto ldgB = [&](int c) {
        prefB[0] = *(const uint4*)((const char*)(Wt + (size_t)(n0 + brow)  * K + c * 32) + bv4  * 16);
        prefB[1] = *(const uint4*)((const char*)(Wt + (size_t)(n0 + brow2) * K + c * 32) + bv42 * 16);
    };
    auto stsB = [&](__half* Bbuf) {
        *(uint4*)((char*)(Bbuf + brow  * TPITCH_H) + bv4  * 16) = prefB[0];
        *(uint4*)((char*)(Bbuf + brow2 * TPITCH_H) + bv42 * 16) = prefB[1];
    };

    const int NC = K >> 5;
    ldgA(0); ldgB(0);
    for (int c = 0; c < NC; c++) {
        stsA(AsA[c & 1]);
        stsB(BsA[c & 1]);
        if (c + 1 < NC) { ldgA(c + 1); ldgB(c + 1); }
        __syncthreads();
        chunk_f16<2>(AsA[c & 1], TPITCH_H, BsA[c & 1], wm, wn, g, r, acc);
    }
    __syncthreads();

#pragma unroll
    for (int mt = 0; mt < 2; mt++) {
        int rw0 = wm + mt * 16 + g;
#pragma unroll
        for (int nt = 0; nt < 8; nt++) {
            int col = wn + nt * 8 + 2 * r;
            *(float2*)(stage + rw0 * 132 + col)       = make_float2(acc[mt][nt][0], acc[mt][nt][1]);
            *(float2*)(stage + (rw0 + 8) * 132 + col) = make_float2(acc[mt][nt][2], acc[mt][nt][3]);
        }
    }
    __syncthreads();

    if (EPI == EPI_RELU) {
        // bias + relu folded into coalesced fp16 mirror write
        mirror_stage(stage, outh + (size_t)m0 * ldo, ldo, n0, bias, tid);
    } else {  // EPI_LNRES (ldo == 128) + coalesced fp16 mirror
        float4 gg  = *(const float4*)(lng + lane * 4);
        float4 bbn = *(const float4*)(lnb + lane * 4);
        float4 bz  = *(const float4*)(bias + lane * 4);
        for (int rr = wid; rr < 128; rr += 8) {
            float4 res = *(const float4*)(resid + (size_t)(m0 + rr) * 128 + lane * 4);
            float4 d   = *(float4*)(stage + rr * 132 + lane * 4);
            float v0 = res.x + d.x + bz.x, v1 = res.y + d.y + bz.y;
            float v2 = res.z + d.z + bz.z, v3 = res.w + d.w + bz.w;
            float sum = v0 + v1 + v2 + v3;
#pragma unroll
            for (int off = 16; off > 0; off >>= 1)
                sum += __shfl_xor_sync(0xffffffffu, sum, off);
            float mean = sum * (1.0f / 128.0f);
            float d0 = v0 - mean, d1 = v1 - mean, d2 = v2 - mean, d3 = v3 - mean;
            float sq = d0 * d0 + d1 * d1 + d2 * d2 + d3 * d3;
#pragma unroll
            for (int off = 16; off > 0; off >>= 1)
                sq += __shfl_xor_sync(0xffffffffu, sq, off);
            float inv = rsqrtf(sq * (1.0f / 128.0f) + 1e-5f);
            float4 o;
            o.x = d0 * inv * gg.x + bbn.x;
            o.y = d1 * inv * gg.y + bbn.y;
            o.z = d2 * inv * gg.z + bbn.z;
            o.w = d3 * inv * gg.w + bbn.w;
            *(float4*)(out + (size_t)(m0 + rr) * 128 + lane * 4) = o;
            *(float4*)(stage + rr * 132 + lane * 4) = o;
        }
        __syncthreads();
        mirror_stage(stage, outh + (size_t)m0 * 128, 128, 0, nullptr, tid);
    }
}

// -------- standalone LayerNorm (norm0) + coalesced fp16 mirror -------------
__global__ void ln_k(float* __restrict__ io, __half* __restrict__ ioh,
                     const float* __restrict__ add,
                     const float* __restrict__ scale,
                     const float* __restrict__ g, const float* __restrict__ b,
                     int rows)
{
    __shared__ float sbuf[8][128];
    int w    = threadIdx.x >> 5;
    int lane = threadIdx.x & 31;
    int row  = blockIdx.x * 8 + w;
    if (row >= rows) return;
    float s = scale ? scale[row] : 1.0f;

    float4 x = *(const float4*)(io  + (size_t)row * 128 + lane * 4);
    float4 a = *(const float4*)(add + (size_t)row * 128 + lane * 4);
    float v[4] = { x.x + a.x * s, x.y + a.y * s, x.z + a.z * s, x.w + a.w * s };

    float sum = v[0] + v[1] + v[2] + v[3];
#pragma unroll
    for (int off = 16; off > 0; off >>= 1) sum += __shfl_xor_sync(0xffffffffu, sum, off);
    float mean = sum * (1.0f / 128.0f);
    float sq = 0.f;
#pragma unroll
    for (int j = 0; j < 4; j++) { float d = v[j] - mean; sq += d * d; }
#pragma unroll
    for (int off = 16; off > 0; off >>= 1) sq += __shfl_xor_sync(0xffffffffu, sq, off);
    float inv = rsqrtf(sq * (1.0f / 128.0f) + 1e-5f);

    float4 gg = *(const float4*)(g + lane * 4);
    float4 bb = *(const float4*)(b + lane * 4);
    float4 o;
    o.x = (v[0] - mean) * inv * gg.x + bb.x;
    o.y = (v[1] - mean) * inv * gg.y + bb.y;
    o.z = (v[2] - mean) * inv * gg.z + bb.z;
    o.w = (v[3] - mean) * inv * gg.w + bb.w;
    *(float4*)(io + (size_t)row * 128 + lane * 4) = o;
    *(float4*)(&sbuf[w][lane * 4]) = o;
    __syncwarp();
    if (lane < 16) {
        int c = lane >> 2, ww = lane & 3;
        int s2 = ww >> 1, h8 = ww & 1;
        const float* srow = sbuf[w] + c * 32 + s2 * 16;
        uint32_t pk[4];
#pragma unroll
        for (int t2 = 0; t2 < 4; t2++) {
            int p0 = h8 * 8 + t2 * 2;
            float v0 = srow[uperm(p0)], v1 = srow[uperm(p0 + 1)];
            __half2 hh = __floats2half2_rn(v0, v1);
            pk[t2] = *(uint32_t*)&hh;
        }
        *(uint4*)(ioh + (size_t)row * 128 + c * 32 + s2 * 16 + h8 * 8) =
            make_uint4(pk[0], pk[1], pk[2], pk[3]);
    }
}

// ------ ONE fused setup kernel: copies + mirrors + zeros + weights ---------
__global__ void setup_all(
    float4* __restrict__ nodes4, const float4* __restrict__ x4,
    float4* __restrict__ edge4, const float4* __restrict__ eattr4,
    __half* __restrict__ nodesh, __half* __restrict__ edgeh,
    float4* __restrict__ agg4, float4* __restrict__ ideg4,
    __half* __restrict__ wt,
    const float* __restrict__ mW0, const float* __restrict__ mW1,
    const float* __restrict__ mW2, const float* __restrict__ fW0,
    const float* __restrict__ fW1, const float* __restrict__ xW0,
    const float* __restrict__ xW1, const float* __restrict__ xW2)
{
    int segy = blockIdx.y;
    int tid0 = blockIdx.x * blockDim.x + threadIdx.x;
    int nthr = gridDim.x * blockDim.x;
    if (segy == 0) {
        for (int i = tid0; i < NNODES * DD / 4; i += nthr) {
            float4 v = x4[i];
            nodes4[i] = v;
            int row = i >> 5, c4 = i & 31;
            put4(nodesh + (size_t)row * 128 + (c4 >> 3) * 32, c4 & 7, v);
        }
    } else if (segy == 1) {
        for (int i = tid0; i < EDGES * DD / 4; i += nthr) {
            float4 v = eattr4[i];
            edge4[i] = v;
            int row = i >> 5, c4 = i & 31;
            put4(edgeh + (size_t)row * 128 + (c4 >> 3) * 32, c4 & 7, v);
        }
    } else if (segy == 2) {
        float4 z = make_float4(0.f, 0.f, 0.f, 0.f);
        for (int i = tid0; i < NNODES * DD / 4; i += nthr) agg4[i] = z;
    } else if (segy == 3) {
        float4 z = make_float4(0.f, 0.f, 0.f, 0.f);
        for (int i = tid0; i < NNODES / 4; i += nthr) ideg4[i] = z;
    } else {
        int seg = (segy - 4) & 7, l = (segy - 4) >> 3;
        int K, N, ofs; const float* src;
        switch (seg) {
          case 0: K=KCAT; N=DD;  ofs=0;      src=mW0 + (size_t)l*KCAT*DD; break;
          case 1: K=DD;   N=DD;  ofs=49152;  src=mW1 + (size_t)l*DD*DD;  break;
          case 2: K=DD;   N=DD;  ofs=65536;  src=mW2 + (size_t)l*DD*DD;  break;
          case 3: K=DD;   N=FFH; ofs=81920;  src=fW0 + (size_t)l*DD*FFH; break;
          case 4: K=FFH;  N=DD;  ofs=147456; src=fW1 + (size_t)l*FFH*DD; break;
          case 5: K=KCAT; N=DD;  ofs=212992; src=xW0 + (size_t)l*KCAT*DD; break;
          case 6: K=DD;   N=DD;  ofs=262144; src=xW1 + (size_t)l*DD*DD;  break;
          default:K=DD;   N=DD;  ofs=278528; src=xW2 + (size_t)l*DD*DD;  break;
        }
        __half* dst = wt + (size_t)l * WT_PER_LAYER + ofs;
        int total = K * N;
        for (int i = tid0; i < total; i += nthr) {
            int n = i / K, rem = i - n * K;
            int c = rem >> 5, t = rem & 31;
            int s = t >> 4, p = t & 15;
            int rr = p >> 2, q = p & 3;
            int u = 2 * rr + (q & 1) + 8 * (q >> 1);
            int k = c * 32 + s * 16 + u;
            dst[i] = __float2half_rn(src[(size_t)k * N + n]);
        }
    }
}

// ---------------- small helpers ----------------
__global__ void zero_k(float4* __restrict__ p, int n4) {
    for (int i = blockIdx.x * blockDim.x + threadIdx.x; i < n4; i += gridDim.x * blockDim.x)
        p[i] = make_float4(0.f, 0.f, 0.f, 0.f);
}
__global__ void deg_k(const int* __restrict__ dst, float* __restrict__ deg) {
    int e = blockIdx.x * blockDim.x + threadIdx.x;
    if (e < EDGES) atomicAdd(&deg[dst[e]], 1.0f);
}
__global__ void invdeg_k(float* __restrict__ deg) {
    int i = blockIdx.x * blockDim.x + threadIdx.x;
    if (i < NNODES) deg[i] = 1.0f / fmaxf(deg[i], 1.0f);
}

// ---------------- launch ----------------
extern "C" void kernel_launch(void* const* d_in, const int* in_sizes, int n_in,
                              void* d_out, int out_size)
{
    const float* x        = (const float*)d_in[0];
    const int*   eidx     = (const int*)  d_in[1];
    const float* eattr_in = (const float*)d_in[2];
    const float* msg_W0 = (const float*)d_in[3];
    const float* msg_b0 = (const float*)d_in[4];
    const float* msg_W1 = (const float*)d_in[5];
    const float* msg_b1 = (const float*)d_in[6];
    const float* msg_W2 = (const float*)d_in[7];
    const float* msg_b2 = (const float*)d_in[8];
    const float* n0g    = (const float*)d_in[9];
    const float* n0b    = (const float*)d_in[10];
    const float* ff_W0  = (const float*)d_in[11];
    const float* ff_b0  = (const float*)d_in[12];
    const float* ff_W1  = (const float*)d_in[13];
    const float* ff_b1  = (const float*)d_in[14];
    const float* n1g    = (const float*)d_in[15];
    const float* n1b    = (const float*)d_in[16];
    const float* eW0    = (const float*)d_in[17];
    const float* eb0    = (const float*)d_in[18];
    const float* eW1    = (const float*)d_in[19];
    const float* eb1    = (const float*)d_in[20];
    const float* eW2    = (const float*)d_in[21];
    const float* eb2    = (const float*)d_in[22];
    const float* eng    = (const float*)d_in[23];
    const float* enb    = (const float*)d_in[24];

    float* nodes = (float*)d_out;
    const int* src = eidx;
    const int* dst = eidx + EDGES;

    static bool init = false;
    static float *edge, *agg, *ideg;
    static __half *wt, *nodesh, *edgeh, *ffh;
    if (!init) {
        cudaGetSymbolAddress((void**)&edge,   g_edge);
        cudaGetSymbolAddress((void**)&agg,    g_agg);
        cudaGetSymbolAddress((void**)&ideg,   g_ideg);
        cudaGetSymbolAddress((void**)&wt,     g_wt);
        cudaGetSymbolAddress((void**)&nodesh, g_nodesh);
        cudaGetSymbolAddress((void**)&edgeh,  g_edgeh);
        cudaGetSymbolAddress((void**)&ffh,    g_ffh);
        cudaFuncSetAttribute(mlp3_tc<EPI_ATOMIC>,
                             cudaFuncAttributeMaxDynamicSharedMemorySize, DYN_MLP);
        cudaFuncSetAttribute(mlp3_tc<EPI_LNRES>,
                             cudaFuncAttributeMaxDynamicSharedMemorySize, DYN_MLP);
        cudaFuncSetAttribute(gemm_tc<EPI_RELU>,
                             cudaFuncAttributeMaxDynamicSharedMemorySize, DYN_GEMM);
        cudaFuncSetAttribute(gemm_tc<EPI_LNRES>,
                             cudaFuncAttributeMaxDynamicSharedMemorySize, DYN_GEMM);
        init = true;
    }

    setup_all<<<dim3(256, 20), 256>>>(
        (float4*)nodes, (const float4*)x, (float4*)edge, (const float4*)eattr_in,
        nodesh, edgeh, (float4*)agg, (float4*)ideg, wt,
        msg_W0, msg_W1, msg_W2, ff_W0, ff_W1, eW0, eW1, eW2);       // 0
    deg_k<<<EDGES / 256, 256>>>(dst, ideg);                         // 1
    invdeg_k<<<NNODES / 256, 256>>>(ideg);                          // 2

    const dim3 gE(EDGES / 128, 1), gN(NNODES / 128, 1), gF(NNODES / 128, FFH / 128);

    for (int l = 0; l < LAYERS; l++) {
        __half* wl = wt + (size_t)l * WT_PER_LAYER;
        const int O_MW0 = 0, O_MW1 = 49152, O_MW2 = 65536, O_FW0 = 81920,
                  O_FW1 = 147456, O_EW0 = 212992, O_EW1 = 262144, O_EW2 = 278528;

        if (l > 0) zero_k<<<4096, 256>>>((float4*)agg, NNODES * DD / 4);
        mlp3_tc<EPI_ATOMIC><<<gE, 256, DYN_MLP>>>(                   // 3 (l=0) <- ncu
            nodesh, edgeh, src, dst,
            wl + O_MW0, msg_b0 + l * DD, wl + O_MW1, msg_b1 + l * DD,
            wl + O_MW2, msg_b2 + l * DD,
            agg, nullptr, nullptr, nullptr, nullptr);
        ln_k<<<NNODES / 8, 256>>>(nodes, nodesh, agg, ideg,
                                  n0g + l * DD, n0b + l * DD, NNODES);

        gemm_tc<EPI_RELU><<<gF, 256, DYN_GEMM>>>(
            nodesh, DD, DD, wl + O_FW0, ff_b0 + l * FFH,
            nullptr, ffh, FFH, nullptr, nullptr, nullptr);
        gemm_tc<EPI_LNRES><<<gN, 256, DYN_GEMM>>>(
            ffh, FFH, FFH, wl + O_FW1, ff_b1 + l * DD,
            nodes, nodesh, DD, nodes, n1g + l * DD, n1b + l * DD);

        mlp3_tc<EPI_LNRES><<<gE, 256, DYN_MLP>>>(
            nodesh, edgeh, src, dst,
            wl + O_EW0, eb0 + l * DD, wl + O_EW1, eb1 + l * DD,
            wl + O_EW2, eb2 + l * DD,
            edge, edgeh, edge, eng + l * DD, enb + l * DD);
    }
    // nodes (= d_out) holds the final [B, N, D] result.
}

// round 15
// speedup vs baseline: 1.2420x; 1.2420x over previous
#include <cuda_runtime.h>
#include <cuda_fp16.h>
#include <cstdint>

// ---------------- problem constants ----------------
#define EDGES   262144
#define NNODES  32768
#define DD      128
#define FFH     512
#define LAYERS  2
#define KCAT    384

#define WT_PER_LAYER 294912

// ---------------- scratch ----------------
__device__ float  g_edge[EDGES * DD];
__device__ float  g_agg [NNODES * DD];
__device__ float  g_ff  [NNODES * FFH];
__device__ float  g_ideg[NNODES];
__device__ float  g_P   [NNODES * 256];    // [ nodes@W0a | nodes@W0c ]
__device__ __half g_wt  [LAYERS * WT_PER_LAYER];

enum { EPI_RELU = 0, EPI_ATOMIC = 1, EPI_LNRES = 2, EPI_STORE = 3 };

#define TPITCH_H 48            // halves per tile row (96 B)
#define HROW_H   208           // halves per HA row (4 chunks * 48 + pad)
static const int TILE_BYTES = 128 * TPITCH_H * 2;   // 12288
static const int HA_BYTES   = 128 * HROW_H * 2;     // 53248
static const int STAGE_B    = 128 * 132 * 4;        // 67584
static const int DYN_MLP    = HA_BYTES + 2 * TILE_BYTES + 1024;   // 78848
static const int DYN_GEMM   = STAGE_B + 1024;                     // 68608

// ---------------- device helpers ----------------
__device__ __forceinline__ void mma16(float* d, uint32_t a0, uint32_t a1,
                                      uint32_t a2, uint32_t a3,
                                      uint32_t b0, uint32_t b1) {
    asm volatile(
        "mma.sync.aligned.m16n8k16.row.col.f32.f16.f16.f32 "
        "{%0,%1,%2,%3}, {%4,%5,%6,%7}, {%8,%9}, {%0,%1,%2,%3};"
        : "+f"(d[0]), "+f"(d[1]), "+f"(d[2]), "+f"(d[3])
        : "r"(a0), "r"(a1), "r"(a2), "r"(a3), "r"(b0), "r"(b1));
}
template <int MT>
__device__ __forceinline__ void chunk_f16(const __half* A, int apitch,
                                          const __half* B,
                                          int wm, int wn, int g, int r,
                                          float acc[][8][4]) {
#pragma unroll
    for (int s = 0; s < 2; s++) {
        uint2 alo[MT], ahi[MT];
#pragma unroll
        for (int mt = 0; mt < MT; mt++) {
            const __half* p0 = A + (wm + mt * 16 + g) * apitch + s * 16 + r * 4;
            alo[mt] = *(const uint2*)p0;
            ahi[mt] = *(const uint2*)(p0 + 8 * apitch);
        }
        uint2 bf[8];
#pragma unroll
        for (int nt = 0; nt < 8; nt++)
            bf[nt] = *(const uint2*)(B + (wn + nt * 8 + g) * TPITCH_H + s * 16 + r * 4);
#pragma unroll
        for (int mt = 0; mt < MT; mt++)
#pragma unroll
            for (int nt = 0; nt < 8; nt++)
                mma16(acc[mt][nt], alo[mt].x, ahi[mt].x, alo[mt].y, ahi[mt].y,
                      bf[nt].x, bf[nt].y);
    }
}
// write float4 (4 consecutive k at group c4 of a 32-k block) permuted as fp16
__device__ __forceinline__ void put4(__half* blk, int c4, float4 v) {
    int s  = c4 >> 2, jm = c4 & 3;
    int p1 = ((jm & 1) << 3) | ((jm >> 1) << 1);      // 0,8,2,10
    __half* b = blk + s * 16 + p1;
    *(__half2*)b       = __floats2half2_rn(v.x, v.y);
    *(__half2*)(b + 4) = __floats2half2_rn(v.z, v.w);
}
// permuted k within a 128-k block for linear dest position t (0..127)
__device__ __forceinline__ int perm128(int t) {
    int c = t >> 5, tt = t & 31;
    int s = tt >> 4, p = tt & 15;
    int rr = p >> 2, q = p & 3;
    int u = 2 * rr + (q & 1) + 8 * (q >> 1);
    return c * 32 + s * 16 + u;
}

// ---- fused 3-linear MLP over edges with P-decomposition (8w x 32x64) ------
// h1 = relu(edge@W0b + Pa[src] + Pc[dst] + b0); h2 = relu(h1@W1+b1); out stage2
template <int EPI>
__global__ void __launch_bounds__(256, 2)
mlp3_tc(const float* __restrict__ edgef,
        const int* __restrict__ srcI, const int* __restrict__ dstI,
        const float* __restrict__ P,
        const __half* __restrict__ W0b, const float* __restrict__ b0,
        const __half* __restrict__ W1t, const float* __restrict__ b1,
        const __half* __restrict__ W2t, const float* __restrict__ b2,
        float* __restrict__ out, const float* __restrict__ resid,
        const float* __restrict__ lng, const float* __restrict__ lnb)
{
    extern __shared__ char dyn[];
    char*   basep = (char*)(((uintptr_t)dyn + 1023) & ~(uintptr_t)1023);
    __half* HA    = (__half*)basep;                      // [128][HROW_H]
    __half* BsA[2] = { (__half*)(basep + HA_BYTES),
                       (__half*)(basep + HA_BYTES + TILE_BYTES) };
    float*  stage = (float*)basep;                       // reuse, pitch 132

    __shared__ int s_src[128], s_dst[128];

    const int tid  = threadIdx.x;
    const int wid  = tid >> 5;
    const int lane = tid & 31;
    const int g    = lane >> 2;
    const int r    = lane & 3;
    const int wm   = (wid & 3) * 32;
    const int wn   = (wid >> 2) * 64;
    const int m0   = blockIdx.x * 128;

    if (tid < 128) { s_src[tid] = srcI[m0 + tid]; s_dst[tid] = dstI[m0 + tid]; }
    __syncthreads();

    float acc[2][8][4];
#pragma unroll
    for (int mt = 0; mt < 2; mt++)
#pragma unroll
        for (int nt = 0; nt < 8; nt++)
#pragma unroll
            for (int q = 0; q < 4; q++) acc[mt][nt][q] = 0.f;

    int arow[4], acol[4];
#pragma unroll
    for (int i = 0; i < 4; i++) {
        int f4 = tid + i * 256;
        arow[i] = f4 >> 3;
        acol[i] = f4 & 7;
    }
    const int brow = tid >> 2, bv4 = tid & 3;
    const int brow2 = (tid + 256) >> 2, bv42 = (tid + 256) & 3;

    float4 prefA[4];
    uint4  prefB[2];

    auto ldgA = [&](int c) {     // direct coalesced edge rows
#pragma unroll
        for (int i = 0; i < 4; i++)
            prefA[i] = *(const float4*)(edgef + (size_t)(m0 + arow[i]) * 128 +
                                        c * 32 + acol[i] * 4);
    };
    auto stsA = [&](int c) {
        __half* slot = HA + (c & 3) * TPITCH_H;
#pragma unroll
        for (int i = 0; i < 4; i++)
            put4(slot + arow[i] * HROW_H, acol[i], prefA[i]);
    };
    auto ldgB = [&](const __half* Wt, int Kdim, int c) {
        prefB[0] = *(const uint4*)((const char*)(Wt + (size_t)brow  * Kdim + c * 32) + bv4  * 16);
        prefB[1] = *(const uint4*)((const char*)(Wt + (size_t)brow2 * Kdim + c * 32) + bv42 * 16);
    };
    auto stsB = [&](__half* Bbuf) {
        *(uint4*)((char*)(Bbuf + brow  * TPITCH_H) + bv4  * 16) = prefB[0];
        *(uint4*)((char*)(Bbuf + brow2 * TPITCH_H) + bv42 * 16) = prefB[1];
    };
    auto haStore = [&](int row, int col, float v) {
        int c  = col >> 5, u = col & 31;
        int s  = u >> 4, uu = u & 15;
        int rr = (uu & 7) >> 1;
        int qq = (uu & 1) | ((uu >> 3) << 1);
        HA[row * HROW_H + c * TPITCH_H + s * 16 + rr * 4 + qq] = __float2half_rn(v);
    };
    // stage-0 writeback: bias + Pa[src] + Pc[dst] + relu
    auto wbRelu0 = [&]() {
#pragma unroll
        for (int mt = 0; mt < 2; mt++)
#pragma unroll
            for (int h = 0; h < 2; h++) {
                int row = wm + mt * 16 + g + h * 8;
                const float* ps = P + (size_t)s_src[row] * 256;
                const float* pd = P + (size_t)s_dst[row] * 256 + 128;
#pragma unroll
                for (int nt = 0; nt < 8; nt++) {
                    int col0 = wn + nt * 8 + 2 * r;
                    float2 a2 = __ldg((const float2*)(ps + col0));
                    float2 c2 = __ldg((const float2*)(pd + col0));
                    float v0 = fmaxf(acc[mt][nt][h * 2 + 0] + __ldg(b0 + col0) +
                                     a2.x + c2.x, 0.f);
                    float v1 = fmaxf(acc[mt][nt][h * 2 + 1] + __ldg(b0 + col0 + 1) +
                                     a2.y + c2.y, 0.f);
                    haStore(row, col0, v0);
                    haStore(row, col0 + 1, v1);
                    acc[mt][nt][h * 2 + 0] = 0.f;
                    acc[mt][nt][h * 2 + 1] = 0.f;
                }
            }
    };
    auto wbRelu = [&](const float* bias) {
#pragma unroll
        for (int mt = 0; mt < 2; mt++)
#pragma unroll
            for (int q = 0; q < 4; q++) {
                int row = wm + mt * 16 + g + ((q & 2) ? 8 : 0);
#pragma unroll
                for (int nt = 0; nt < 8; nt++) {
                    int col = wn + nt * 8 + 2 * r + (q & 1);
                    float v = fmaxf(acc[mt][nt][q] + __ldg(bias + col), 0.f);
                    haStore(row, col, v);
                    acc[mt][nt][q] = 0.f;
                }
            }
    };

    // ---- stage 0: K = 128 (edge @ W0b), pipelined ----
    ldgA(0); ldgB(W0b, 128, 0);
    for (int c = 0; c < 4; c++) {
        stsA(c);
        stsB(BsA[c & 1]);
        if (c < 3) { ldgA(c + 1); ldgB(W0b, 128, c + 1); }
        __syncthreads();
        chunk_f16<2>(HA + (c & 3) * TPITCH_H, HROW_H, BsA[c & 1], wm, wn, g, r, acc);
    }
    __syncthreads();
    wbRelu0();

    // ---- stage 1: K = 128, A resident in HA ----
    ldgB(W1t, 128, 0);
    for (int c = 0; c < 4; c++) {
        stsB(BsA[c & 1]);
        if (c < 3) ldgB(W1t, 128, c + 1);
        __syncthreads();
        chunk_f16<2>(HA + c * TPITCH_H, HROW_H, BsA[c & 1], wm, wn, g, r, acc);
    }
    __syncthreads();
    wbRelu(b1);

    // ---- stage 2: K = 128 ----
    ldgB(W2t, 128, 0);
    for (int c = 0; c < 4; c++) {
        stsB(BsA[c & 1]);
        if (c < 3) ldgB(W2t, 128, c + 1);
        __syncthreads();
        chunk_f16<2>(HA + c * TPITCH_H, HROW_H, BsA[c & 1], wm, wn, g, r, acc);
    }
    __syncthreads();

    // ---- epilogue (fp32 stage, pitch 132) ----
    if (EPI == EPI_ATOMIC) {
#pragma unroll
        for (int mt = 0; mt < 2; mt++)
#pragma unroll
            for (int q = 0; q < 4; q++) {
                int row = wm + mt * 16 + g + ((q & 2) ? 8 : 0);
#pragma unroll
                for (int nt = 0; nt < 8; nt++) {
                    int col = wn + nt * 8 + 2 * r + (q & 1);
                    stage[row * 132 + col] = acc[mt][nt][q] + __ldg(b2 + col);
                }
            }
        __syncthreads();
#pragma unroll
        for (int it = 0; it < 16; it++) {
            int f4  = it * 256 + tid;
            int row = f4 >> 5;
            int c4  = f4 & 31;
            float4 v = *(float4*)(stage + row * 132 + c4 * 4);
            float* dbase = out + (size_t)s_dst[row] * 128 + c4 * 4;
            asm volatile("red.global.add.v4.f32 [%0], {%1,%2,%3,%4};"
                         :: "l"(dbase), "f"(v.x), "f"(v.y), "f"(v.z), "f"(v.w)
                         : "memory");
        }
    } else {  // EPI_LNRES: out = LN(resid + acc + b2)
#pragma unroll
        for (int mt = 0; mt < 2; mt++)
#pragma unroll
            for (int q = 0; q < 4; q++) {
                int row = wm + mt * 16 + g + ((q & 2) ? 8 : 0);
#pragma unroll
                for (int nt = 0; nt < 8; nt++) {
                    int col = wn + nt * 8 + 2 * r + (q & 1);
                    stage[row * 132 + col] = acc[mt][nt][q];
                }
            }
        __syncthreads();
        float4 gg  = *(const float4*)(lng + lane * 4);
        float4 bbn = *(const float4*)(lnb + lane * 4);
        float4 bz  = *(const float4*)(b2 + lane * 4);
        for (int rr = wid; rr < 128; rr += 8) {
            float4 res = *(const float4*)(resid + (size_t)(m0 + rr) * 128 + lane * 4);
            float4 d   = *(float4*)(stage + rr * 132 + lane * 4);
            float v0 = res.x + d.x + bz.x, v1 = res.y + d.y + bz.y;
            float v2 = res.z + d.z + bz.z, v3 = res.w + d.w + bz.w;
            float sum = v0 + v1 + v2 + v3;
#pragma unroll
            for (int off = 16; off > 0; off >>= 1)
                sum += __shfl_xor_sync(0xffffffffu, sum, off);
            float mean = sum * (1.0f / 128.0f);
            float d0 = v0 - mean, d1 = v1 - mean, d2 = v2 - mean, d3 = v3 - mean;
            float sq = d0 * d0 + d1 * d1 + d2 * d2 + d3 * d3;
#pragma unroll
            for (int off = 16; off > 0; off >>= 1)
                sq += __shfl_xor_sync(0xffffffffu, sq, off);
            float inv = rsqrtf(sq * (1.0f / 128.0f) + 1e-5f);
            float4 o;
            o.x = d0 * inv * gg.x + bbn.x;
            o.y = d1 * inv * gg.y + bbn.y;
            o.z = d2 * inv * gg.z + bbn.z;
            o.w = d3 * inv * gg.w + bbn.w;
            *(float4*)(out + (size_t)(m0 + rr) * 128 + lane * 4) = o;
        }
    }
}

// ---------------- dense GEMM (fp32 A, fp16 weights), reg-prefetched --------
template <int EPI>
__global__ void __launch_bounds__(256, 2)
gemm_tc(const float* __restrict__ A, int lda, int K,
        const __half* __restrict__ Wt, const float* __restrict__ bias,
        float* __restrict__ out, int ldo,
        const float* __restrict__ resid,
        const float* __restrict__ lng, const float* __restrict__ lnb)
{
    extern __shared__ char dyn[];
    char*   base  = (char*)(((uintptr_t)dyn + 1023) & ~(uintptr_t)1023);
    __half* AsA[2] = { (__half*)base, (__half*)(base + TILE_BYTES) };
    __half* BsA[2] = { (__half*)(base + 2 * TILE_BYTES),
                       (__half*)(base + 3 * TILE_BYTES) };
    float*  stage = (float*)base;

    const int tid  = threadIdx.x;
    const int wid  = tid >> 5;
    const int lane = tid & 31;
    const int g    = lane >> 2;
    const int r    = lane & 3;
    const int wm   = (wid & 3) * 32;
    const int wn   = (wid >> 2) * 64;
    const int m0   = blockIdx.x * 128;
    const int n0   = blockIdx.y * 128;

    float acc[2][8][4];
#pragma unroll
    for (int mt = 0; mt < 2; mt++)
#pragma unroll
        for (int nt = 0; nt < 8; nt++)
#pragma unroll
            for (int q = 0; q < 4; q++) acc[mt][nt][q] = 0.f;

    int arow[4], acol[4];
#pragma unroll
    for (int i = 0; i < 4; i++) {
        int f4 = tid + i * 256;
        arow[i] = f4 >> 3;
        acol[i] = f4 & 7;
    }
    const int brow = tid >> 2, bv4 = tid & 3;
    const int brow2 = (tid + 256) >> 2, bv42 = (tid + 256) & 3;

    float4 prefA[4];
    uint4  prefB[2];

    auto ldgA = [&](int c) {
#pragma unroll
        for (int i = 0; i < 4; i++)
            prefA[i] = *(const float4*)(A + (size_t)(m0 + arow[i]) * lda + c * 32 + acol[i] * 4);
    };
    auto stsA = [&](__half* Abuf) {
#pragma unroll
        for (int i = 0; i < 4; i++)
            put4(Abuf + arow[i] * TPITCH_H, acol[i], prefA[i]);
    };
    auto ldgB = [&](int c) {
        prefB[0] = *(const uint4*)((const char*)(Wt + (size_t)(n0 + brow)  * K + c * 32) + bv4  * 16);
        prefB[1] = *(const uint4*)((const char*)(Wt + (size_t)(n0 + brow2) * K + c * 32) + bv42 * 16);
    };
    auto stsB = [&](__half* Bbuf) {
        *(uint4*)((char*)(Bbuf + brow  * TPITCH_H) + bv4  * 16) = prefB[0];
        *(uint4*)((char*)(Bbuf + brow2 * TPITCH_H) + bv42 * 16) = prefB[1];
    };

    const int NC = K >> 5;
    ldgA(0); ldgB(0);
    for (int c = 0; c < NC; c++) {
        stsA(AsA[c & 1]);
        stsB(BsA[c & 1]);
        if (c + 1 < NC) { ldgA(c + 1); ldgB(c + 1); }
        __syncthreads();
        chunk_f16<2>(AsA[c & 1], TPITCH_H, BsA[c & 1], wm, wn, g, r, acc);
    }
    __syncthreads();

#pragma unroll
    for (int mt = 0; mt < 2; mt++) {
        int rw0 = wm + mt * 16 + g;
#pragma unroll
        for (int nt = 0; nt < 8; nt++) {
            int col = wn + nt * 8 + 2 * r;
            *(float2*)(stage + rw0 * 132 + col)       = make_float2(acc[mt][nt][0], acc[mt][nt][1]);
            *(float2*)(stage + (rw0 + 8) * 132 + col) = make_float2(acc[mt][nt][2], acc[mt][nt][3]);
        }
    }
    __syncthreads();

    if (EPI == EPI_STORE) {
#pragma unroll
        for (int it = 0; it < 16; it++) {
            int f4  = it * 256 + tid;
            int row = f4 >> 5;
            int c4  = f4 & 31;
            float4 v = *(float4*)(stage + row * 132 + c4 * 4);
            *(float4*)(out + (size_t)(m0 + row) * ldo + n0 + c4 * 4) = v;
        }
    } else if (EPI == EPI_RELU) {
#pragma unroll
        for (int it = 0; it < 16; it++) {
            int f4  = it * 256 + tid;
            int row = f4 >> 5;
            int c4  = f4 & 31;
            float4 v  = *(float4*)(stage + row * 132 + c4 * 4);
            float4 bb = *(const float4*)(bias + n0 + c4 * 4);
            v.x = fmaxf(v.x + bb.x, 0.f); v.y = fmaxf(v.y + bb.y, 0.f);
            v.z = fmaxf(v.z + bb.z, 0.f); v.w = fmaxf(v.w + bb.w, 0.f);
            *(float4*)(out + (size_t)(m0 + row) * ldo + n0 + c4 * 4) = v;
        }
    } else {  // EPI_LNRES
        float4 gg  = *(const float4*)(lng + lane * 4);
        float4 bbn = *(const float4*)(lnb + lane * 4);
        float4 bz  = *(const float4*)(bias + lane * 4);
        for (int rr = wid; rr < 128; rr += 8) {
            float4 res = *(const float4*)(resid + (size_t)(m0 + rr) * 128 + lane * 4);
            float4 d   = *(float4*)(stage + rr * 132 + lane * 4);
            float v0 = res.x + d.x + bz.x, v1 = res.y + d.y + bz.y;
            float v2 = res.z + d.z + bz.z, v3 = res.w + d.w + bz.w;
            float sum = v0 + v1 + v2 + v3;
#pragma unroll
            for (int off = 16; off > 0; off >>= 1)
                sum += __shfl_xor_sync(0xffffffffu, sum, off);
            float mean = sum * (1.0f / 128.0f);
            float d0 = v0 - mean, d1 = v1 - mean, d2 = v2 - mean, d3 = v3 - mean;
            float sq = d0 * d0 + d1 * d1 + d2 * d2 + d3 * d3;
#pragma unroll
            for (int off = 16; off > 0; off >>= 1)
                sq += __shfl_xor_sync(0xffffffffu, sq, off);
            float inv = rsqrtf(sq * (1.0f / 128.0f) + 1e-5f);
            float4 o;
            o.x = d0 * inv * gg.x + bbn.x;
            o.y = d1 * inv * gg.y + bbn.y;
            o.z = d2 * inv * gg.z + bbn.z;
            o.w = d3 * inv * gg.w + bbn.w;
            *(float4*)(out + (size_t)(m0 + rr) * 128 + lane * 4) = o;
        }
    }
}

// ---------------- standalone LayerNorm (norm0) ----------------
__global__ void ln_k(float* __restrict__ io, const float* __restrict__ add,
                     const float* __restrict__ scale,
                     const float* __restrict__ g, const float* __restrict__ b,
                     int rows)
{
    int row  = blockIdx.x * 8 + (threadIdx.x >> 5);
    int lane = threadIdx.x & 31;
    if (row >= rows) return;
    float s = scale ? scale[row] : 1.0f;

    float4 x = *(const float4*)(io  + (size_t)row * 128 + lane * 4);
    float4 a = *(const float4*)(add + (size_t)row * 128 + lane * 4);
    float v[4] = { x.x + a.x * s, x.y + a.y * s, x.z + a.z * s, x.w + a.w * s };

    float sum = v[0] + v[1] + v[2] + v[3];
#pragma unroll
    for (int off = 16; off > 0; off >>= 1) sum += __shfl_xor_sync(0xffffffffu, sum, off);
    float mean = sum * (1.0f / 128.0f);
    float sq = 0.f;
#pragma unroll
    for (int j = 0; j < 4; j++) { float d = v[j] - mean; sq += d * d; }
#pragma unroll
    for (int off = 16; off > 0; off >>= 1) sq += __shfl_xor_sync(0xffffffffu, sq, off);
    float inv = rsqrtf(sq * (1.0f / 128.0f) + 1e-5f);

    float4 gg = *(const float4*)(g + lane * 4);
    float4 bb = *(const float4*)(b + lane * 4);
    float4 o;
    o.x = (v[0] - mean) * inv * gg.x + bb.x;
    o.y = (v[1] - mean) * inv * gg.y + bb.y;
    o.z = (v[2] - mean) * inv * gg.z + bb.z;
    o.w = (v[3] - mean) * inv * gg.w + bb.w;
    *(float4*)(io + (size_t)row * 128 + lane * 4) = o;
}

// ------ ONE fused setup kernel: copies + zeros + weight fp16/permute -------
// W0 weights (KCAT) are split: [0,32768) = [A|C] rows (256 x 128 K-major),
// [32768,49152) = B rows (128 x 128).
__global__ void setup_all(
    float4* __restrict__ nodes4, const float4* __restrict__ x4,
    float4* __restrict__ edge4, const float4* __restrict__ eattr4,
    float4* __restrict__ agg4, float4* __restrict__ ideg4,
    __half* __restrict__ wt,
    const float* __restrict__ mW0, const float* __restrict__ mW1,
    const float* __restrict__ mW2, const float* __restrict__ fW0,
    const float* __restrict__ fW1, const float* __restrict__ xW0,
    const float* __restrict__ xW1, const float* __restrict__ xW2)
{
    int segy = blockIdx.y;
    int tid0 = blockIdx.x * blockDim.x + threadIdx.x;
    int nthr = gridDim.x * blockDim.x;
    if (segy == 0) {
        for (int i = tid0; i < NNODES * DD / 4; i += nthr) nodes4[i] = x4[i];
    } else if (segy == 1) {
        for (int i = tid0; i < EDGES * DD / 4; i += nthr) edge4[i] = eattr4[i];
    } else if (segy == 2) {
        float4 z = make_float4(0.f, 0.f, 0.f, 0.f);
        for (int i = tid0; i < NNODES * DD / 4; i += nthr) agg4[i] = z;
    } else if (segy == 3) {
        float4 z = make_float4(0.f, 0.f, 0.f, 0.f);
        for (int i = tid0; i < NNODES / 4; i += nthr) ideg4[i] = z;
    } else {
        int seg = (segy - 4) & 7, l = (segy - 4) >> 3;
        int K, N, ofs; const float* src;
        switch (seg) {
          case 0: K=KCAT; N=DD;  ofs=0;      src=mW0 + (size_t)l*KCAT*DD; break;
          case 1: K=DD;   N=DD;  ofs=49152;  src=mW1 + (size_t)l*DD*DD;  break;
          case 2: K=DD;   N=DD;  ofs=65536;  src=mW2 + (size_t)l*DD*DD;  break;
          case 3: K=DD;   N=FFH; ofs=81920;  src=fW0 + (size_t)l*DD*FFH; break;
          case 4: K=FFH;  N=DD;  ofs=147456; src=fW1 + (size_t)l*FFH*DD; break;
          case 5: K=KCAT; N=DD;  ofs=212992; src=xW0 + (size_t)l*KCAT*DD; break;
          case 6: K=DD;   N=DD;  ofs=262144; src=xW1 + (size_t)l*DD*DD;  break;
          default:K=DD;   N=DD;  ofs=278528; src=xW2 + (size_t)l*DD*DD;  break;
        }
        __half* dst = wt + (size_t)l * WT_PER_LAYER + ofs;
        if (K == KCAT) {
            // split layout
            for (int i = tid0; i < 49152; i += nthr) {
                int ksrc, n;
                if (i < 32768) {
                    int row = i >> 7, t = i & 127;
                    n = row & 127;
                    int kbase = (row >> 7) ? 256 : 0;   // a rows 0..127, c rows 128..255
                    ksrc = kbase + perm128(t);
                } else {
                    int j = i - 32768;
                    n = j >> 7;
                    ksrc = 128 + perm128(j & 127);
                }
                dst[i] = __float2half_rn(src[(size_t)ksrc * DD + n]);
            }
        } else {
            int total = K * N;
            for (int i = tid0; i < total; i += nthr) {
                int n = i / K, rem = i - n * K;
                int c = rem >> 5, t = rem & 31;
                int s = t >> 4, p = t & 15;
                int rr = p >> 2, q = p & 3;
                int u = 2 * rr + (q & 1) + 8 * (q >> 1);
                int k = c * 32 + s * 16 + u;
                dst[i] = __float2half_rn(src[(size_t)k * N + n]);
            }
        }
    }
}

// ---------------- small helpers ----------------
__global__ void zero_k(float4* __restrict__ p, int n4) {
    for (int i = blockIdx.x * blockDim.x + threadIdx.x; i < n4; i += gridDim.x * blockDim.x)
        p[i] = make_float4(0.f, 0.f, 0.f, 0.f);
}
__global__ void deg_k(const int* __restrict__ dst, float* __restrict__ deg) {
    int e = blockIdx.x * blockDim.x + threadIdx.x;
    if (e < EDGES) atomicAdd(&deg[dst[e]], 1.0f);
}
__global__ void invdeg_k(float* __restrict__ deg) {
    int i = blockIdx.x * blockDim.x + threadIdx.x;
    if (i < NNODES) deg[i] = 1.0f / fmaxf(deg[i], 1.0f);
}

// ---------------- launch ----------------
extern "C" void kernel_launch(void* const* d_in, const int* in_sizes, int n_in,
                              void* d_out, int out_size)
{
    const float* x        = (const float*)d_in[0];
    const int*   eidx     = (const int*)  d_in[1];
    const float* eattr_in = (const float*)d_in[2];
    const float* msg_W0 = (const float*)d_in[3];
    const float* msg_b0 = (const float*)d_in[4];
    const float* msg_W1 = (const float*)d_in[5];
    const float* msg_b1 = (const float*)d_in[6];
    const float* msg_W2 = (const float*)d_in[7];
    const float* msg_b2 = (const float*)d_in[8];
    const float* n0g    = (const float*)d_in[9];
    const float* n0b    = (const float*)d_in[10];
    const float* ff_W0  = (const float*)d_in[11];
    const float* ff_b0  = (const float*)d_in[12];
    const float* ff_W1  = (const float*)d_in[13];
    const float* ff_b1  = (const float*)d_in[14];
    const float* n1g    = (const float*)d_in[15];
    const float* n1b    = (const float*)d_in[16];
    const float* eW0    = (const float*)d_in[17];
    const float* eb0    = (const float*)d_in[18];
    const float* eW1    = (const float*)d_in[19];
    const float* eb1    = (const float*)d_in[20];
    const float* eW2    = (const float*)d_in[21];
    const float* eb2    = (const float*)d_in[22];
    const float* eng    = (const float*)d_in[23];
    const float* enb    = (const float*)d_in[24];

    float* nodes = (float*)d_out;
    const int* src = eidx;
    const int* dst = eidx + EDGES;

    static bool init = false;
    static float *edge, *agg, *ffb, *ideg, *P;
    static __half* wt;
    if (!init) {
        cudaGetSymbolAddress((void**)&edge, g_edge);
        cudaGetSymbolAddress((void**)&agg,  g_agg);
        cudaGetSymbolAddress((void**)&ffb,  g_ff);
        cudaGetSymbolAddress((void**)&ideg, g_ideg);
        cudaGetSymbolAddress((void**)&P,    g_P);
        cudaGetSymbolAddress((void**)&wt,   g_wt);
        cudaFuncSetAttribute(mlp3_tc<EPI_ATOMIC>,
                             cudaFuncAttributeMaxDynamicSharedMemorySize, DYN_MLP);
        cudaFuncSetAttribute(mlp3_tc<EPI_LNRES>,
                             cudaFuncAttributeMaxDynamicSharedMemorySize, DYN_MLP);
        cudaFuncSetAttribute(gemm_tc<EPI_RELU>,
                             cudaFuncAttributeMaxDynamicSharedMemorySize, DYN_GEMM);
        cudaFuncSetAttribute(gemm_tc<EPI_LNRES>,
                             cudaFuncAttributeMaxDynamicSharedMemorySize, DYN_GEMM);
        cudaFuncSetAttribute(gemm_tc<EPI_STORE>,
                             cudaFuncAttributeMaxDynamicSharedMemorySize, DYN_GEMM);
        init = true;
    }

    setup_all<<<dim3(256, 20), 256>>>(
        (float4*)nodes, (const float4*)x, (float4*)edge, (const float4*)eattr_in,
        (float4*)agg, (float4*)ideg, wt,
        msg_W0, msg_W1, msg_W2, ff_W0, ff_W1, eW0, eW1, eW2);
    deg_k<<<EDGES / 256, 256>>>(dst, ideg);
    invdeg_k<<<NNODES / 256, 256>>>(ideg);

    const dim3 gE(EDGES / 128, 1), gN(NNODES / 128, 1), gF(NNODES / 128, FFH / 128);
    const dim3 gP(NNODES / 128, 2);

    for (int l = 0; l < LAYERS; l++) {
        __half* wl = wt + (size_t)l * WT_PER_LAYER;
        const int O_MW0 = 0, O_MW1 = 49152, O_MW2 = 65536, O_FW0 = 81920,
                  O_FW1 = 147456, O_EW0 = 212992, O_EW1 = 262144, O_EW2 = 278528;

        if (l > 0) zero_k<<<4096, 256>>>((float4*)agg, NNODES * DD / 4);

        // P = nodes @ [W0a | W0c] for the message MLP
        gemm_tc<EPI_STORE><<<gP, 256, DYN_GEMM>>>(
            nodes, DD, DD, wl + O_MW0, nullptr, P, 256,
            nullptr, nullptr, nullptr);
        mlp3_tc<EPI_ATOMIC><<<gE, 256, DYN_MLP>>>(
            edge, src, dst, P,
            wl + O_MW0 + 32768, msg_b0 + l * DD,
            wl + O_MW1, msg_b1 + l * DD,
            wl + O_MW2, msg_b2 + l * DD,
            agg, nullptr, nullptr, nullptr);
        ln_k<<<NNODES / 8, 256>>>(nodes, agg, ideg, n0g + l * DD, n0b + l * DD, NNODES);

        gemm_tc<EPI_RELU><<<gF, 256, DYN_GEMM>>>(
            nodes, DD, DD, wl + O_FW0, ff_b0 + l * FFH, ffb, FFH,
            nullptr, nullptr, nullptr);
        gemm_tc<EPI_LNRES><<<gN, 256, DYN_GEMM>>>(
            ffb, FFH, FFH, wl + O_FW1, ff_b1 + l * DD, nodes, DD,
            nodes, n1g + l * DD, n1b + l * DD);

        // P = nodes @ [eW0a | eW0c] for the edge MLP
        gemm_tc<EPI_STORE><<<gP, 256, DYN_GEMM>>>(
            nodes, DD, DD, wl + O_EW0, nullptr, P, 256,
            nullptr, nullptr, nullptr);
        mlp3_tc<EPI_LNRES><<<gE, 256, DYN_MLP>>>(
            edge, src, dst, P,
            wl + O_EW0 + 32768, eb0 + l * DD,
            wl + O_EW1, eb1 + l * DD,
            wl + O_EW2, eb2 + l * DD,
            edge, edge, eng + l * DD, enb + l * DD);
    }
    // nodes (= d_out) holds the final [B, N, D] result.
}

// round 17
// speedup vs baseline: 1.3058x; 1.0514x over previous
#include <cuda_runtime.h>
#include <cuda_fp16.h>
#include <cstdint>

// ---------------- problem constants ----------------
#define EDGES   262144
#define NNODES  32768
#define DD      128
#define FFH     512
#define LAYERS  2
#define KCAT    384

#define WT_PER_LAYER 294912

// ---------------- scratch ----------------
__device__ float  g_edge[EDGES * DD];
__device__ float  g_agg [NNODES * DD];
__device__ float  g_ff  [NNODES * FFH];
__device__ float  g_ideg[NNODES];
__device__ __half g_P   [NNODES * 256];    // fp16 [ nodes@W0a | nodes@W0c ]
__device__ __half g_wt  [LAYERS * WT_PER_LAYER];

enum { EPI_RELU = 0, EPI_ATOMIC = 1, EPI_LNRES = 2, EPI_STORE = 3 };

#define TPITCH_H 48            // halves per tile row (96 B)
#define HROW_H   208           // halves per HA row (4 chunks * 48 + pad)
static const int TILE_BYTES = 128 * TPITCH_H * 2;   // 12288
static const int HA_BYTES   = 128 * HROW_H * 2;     // 53248
static const int STAGE_B    = 128 * 132 * 4;        // 67584
static const int DYN_MLP    = HA_BYTES + 2 * TILE_BYTES + 1024;   // 78848
static const int DYN_GEMM   = STAGE_B + 1024;                     // 68608

// ---------------- device helpers ----------------
__device__ __forceinline__ void mma16(float* d, uint32_t a0, uint32_t a1,
                                      uint32_t a2, uint32_t a3,
                                      uint32_t b0, uint32_t b1) {
    asm volatile(
        "mma.sync.aligned.m16n8k16.row.col.f32.f16.f16.f32 "
        "{%0,%1,%2,%3}, {%4,%5,%6,%7}, {%8,%9}, {%0,%1,%2,%3};"
        : "+f"(d[0]), "+f"(d[1]), "+f"(d[2]), "+f"(d[3])
        : "r"(a0), "r"(a1), "r"(a2), "r"(a3), "r"(b0), "r"(b1));
}
template <int MT>
__device__ __forceinline__ void chunk_f16(const __half* A, int apitch,
                                          const __half* B,
                                          int wm, int wn, int g, int r,
                                          float acc[][8][4]) {
#pragma unroll
    for (int s = 0; s < 2; s++) {
        uint2 alo[MT], ahi[MT];
#pragma unroll
        for (int mt = 0; mt < MT; mt++) {
            const __half* p0 = A + (wm + mt * 16 + g) * apitch + s * 16 + r * 4;
            alo[mt] = *(const uint2*)p0;
            ahi[mt] = *(const uint2*)(p0 + 8 * apitch);
        }
        uint2 bf[8];
#pragma unroll
        for (int nt = 0; nt < 8; nt++)
            bf[nt] = *(const uint2*)(B + (wn + nt * 8 + g) * TPITCH_H + s * 16 + r * 4);
#pragma unroll
        for (int mt = 0; mt < MT; mt++)
#pragma unroll
            for (int nt = 0; nt < 8; nt++)
                mma16(acc[mt][nt], alo[mt].x, ahi[mt].x, alo[mt].y, ahi[mt].y,
                      bf[nt].x, bf[nt].y);
    }
}
// write float4 (4 consecutive k at group c4 of a 32-k block) permuted as fp16
__device__ __forceinline__ void put4(__half* blk, int c4, float4 v) {
    int s  = c4 >> 2, jm = c4 & 3;
    int p1 = ((jm & 1) << 3) | ((jm >> 1) << 1);      // 0,8,2,10
    __half* b = blk + s * 16 + p1;
    *(__half2*)b       = __floats2half2_rn(v.x, v.y);
    *(__half2*)(b + 4) = __floats2half2_rn(v.z, v.w);
}
// permuted k within a 128-k block for linear dest position t (0..127)
__device__ __forceinline__ int perm128(int t) {
    int c = t >> 5, tt = t & 31;
    int s = tt >> 4, p = tt & 15;
    int rr = p >> 2, q = p & 3;
    int u = 2 * rr + (q & 1) + 8 * (q >> 1);
    return c * 32 + s * 16 + u;
}
// vectorized HA store of adjacent output columns (col0 even, col0+1)
__device__ __forceinline__ void haStore2(__half* HA, int row, int col0,
                                         float v0, float v1) {
    int c  = col0 >> 5, u = col0 & 31;
    int s  = u >> 4, uu = u & 15;
    int rr = (uu & 7) >> 1;
    int qq = (uu >> 3) << 1;             // bit0 = 0 (col0 even)
    *(__half2*)(HA + row * HROW_H + c * TPITCH_H + s * 16 + rr * 4 + qq) =
        __floats2half2_rn(v0, v1);
}

// ---- fused 3-linear MLP over edges with P-decomposition (8w x 32x64) ------
template <int EPI>
__global__ void __launch_bounds__(256, 2)
mlp3_tc(const float* __restrict__ edgef,
        const int* __restrict__ srcI, const int* __restrict__ dstI,
        const __half* __restrict__ P,
        const __half* __restrict__ W0b, const float* __restrict__ b0,
        const __half* __restrict__ W1t, const float* __restrict__ b1,
        const __half* __restrict__ W2t, const float* __restrict__ b2,
        float* __restrict__ out, const float* __restrict__ resid,
        const float* __restrict__ lng, const float* __restrict__ lnb)
{
    extern __shared__ char dyn[];
    char*   basep = (char*)(((uintptr_t)dyn + 1023) & ~(uintptr_t)1023);
    __half* HA    = (__half*)basep;                      // [128][HROW_H]
    __half* BsA[2] = { (__half*)(basep + HA_BYTES),
                       (__half*)(basep + HA_BYTES + TILE_BYTES) };
    float*  stage = (float*)basep;                       // reuse, pitch 132

    __shared__ int s_src[128], s_dst[128];

    const int tid  = threadIdx.x;
    const int wid  = tid >> 5;
    const int lane = tid & 31;
    const int g    = lane >> 2;
    const int r    = lane & 3;
    const int wm   = (wid & 3) * 32;
    const int wn   = (wid >> 2) * 64;
    const int m0   = blockIdx.x * 128;

    if (tid < 128) { s_src[tid] = srcI[m0 + tid]; s_dst[tid] = dstI[m0 + tid]; }
    __syncthreads();

    float acc[2][8][4];
#pragma unroll
    for (int mt = 0; mt < 2; mt++)
#pragma unroll
        for (int nt = 0; nt < 8; nt++)
#pragma unroll
            for (int q = 0; q < 4; q++) acc[mt][nt][q] = 0.f;

    int arow[4], acol[4];
#pragma unroll
    for (int i = 0; i < 4; i++) {
        int f4 = tid + i * 256;
        arow[i] = f4 >> 3;
        acol[i] = f4 & 7;
    }
    const int brow = tid >> 2, bv4 = tid & 3;
    const int brow2 = (tid + 256) >> 2, bv42 = (tid + 256) & 3;

    float4 prefA[4];
    uint4  prefB[2];

    auto ldgA = [&](int c) {     // direct coalesced edge rows
#pragma unroll
        for (int i = 0; i < 4; i++)
            prefA[i] = *(const float4*)(edgef + (size_t)(m0 + arow[i]) * 128 +
                                        c * 32 + acol[i] * 4);
    };
    auto stsA = [&](int c) {
        __half* slot = HA + (c & 3) * TPITCH_H;
#pragma unroll
        for (int i = 0; i < 4; i++)
            put4(slot + arow[i] * HROW_H, acol[i], prefA[i]);
    };
    auto ldgB = [&](const __half* Wt, int Kdim, int c) {
        prefB[0] = *(const uint4*)((const char*)(Wt + (size_t)brow  * Kdim + c * 32) + bv4  * 16);
        prefB[1] = *(const uint4*)((const char*)(Wt + (size_t)brow2 * Kdim + c * 32) + bv42 * 16);
    };
    auto stsB = [&](__half* Bbuf) {
        *(uint4*)((char*)(Bbuf + brow  * TPITCH_H) + bv4  * 16) = prefB[0];
        *(uint4*)((char*)(Bbuf + brow2 * TPITCH_H) + bv42 * 16) = prefB[1];
    };
    // stage-0 writeback: bias + Pa[src] + Pc[dst] + relu (half2 P, half2 HA)
    auto wbRelu0 = [&]() {
#pragma unroll
        for (int mt = 0; mt < 2; mt++)
#pragma unroll
            for (int h = 0; h < 2; h++) {
                int row = wm + mt * 16 + g + h * 8;
                const __half* ps = P + (size_t)s_src[row] * 256;
                const __half* pd = P + (size_t)s_dst[row] * 256 + 128;
#pragma unroll
                for (int nt = 0; nt < 8; nt++) {
                    int col0 = wn + nt * 8 + 2 * r;
                    float2 a2 = __half22float2(__ldg((const __half2*)(ps + col0)));
                    float2 c2 = __half22float2(__ldg((const __half2*)(pd + col0)));
                    float v0 = fmaxf(acc[mt][nt][h * 2 + 0] + __ldg(b0 + col0) +
                                     a2.x + c2.x, 0.f);
                    float v1 = fmaxf(acc[mt][nt][h * 2 + 1] + __ldg(b0 + col0 + 1) +
                                     a2.y + c2.y, 0.f);
                    haStore2(HA, row, col0, v0, v1);
                    acc[mt][nt][h * 2 + 0] = 0.f;
                    acc[mt][nt][h * 2 + 1] = 0.f;
                }
            }
    };
    auto wbRelu = [&](const float* bias) {
#pragma unroll
        for (int mt = 0; mt < 2; mt++)
#pragma unroll
            for (int h = 0; h < 2; h++) {
                int row = wm + mt * 16 + g + h * 8;
#pragma unroll
                for (int nt = 0; nt < 8; nt++) {
                    int col0 = wn + nt * 8 + 2 * r;
                    float v0 = fmaxf(acc[mt][nt][h * 2 + 0] + __ldg(bias + col0), 0.f);
                    float v1 = fmaxf(acc[mt][nt][h * 2 + 1] + __ldg(bias + col0 + 1), 0.f);
                    haStore2(HA, row, col0, v0, v1);
                    acc[mt][nt][h * 2 + 0] = 0.f;
                    acc[mt][nt][h * 2 + 1] = 0.f;
                }
            }
    };

    // ---- stage 0: K = 128 (edge @ W0b), pipelined ----
    ldgA(0); ldgB(W0b, 128, 0);
    for (int c = 0; c < 4; c++) {
        stsA(c);
        stsB(BsA[c & 1]);
        if (c < 3) { ldgA(c + 1); ldgB(W0b, 128, c + 1); }
        __syncthreads();
        chunk_f16<2>(HA + (c & 3) * TPITCH_H, HROW_H, BsA[c & 1], wm, wn, g, r, acc);
    }
    __syncthreads();
    wbRelu0();

    // ---- stage 1: K = 128, A resident in HA ----
    ldgB(W1t, 128, 0);
    for (int c = 0; c < 4; c++) {
        stsB(BsA[c & 1]);
        if (c < 3) ldgB(W1t, 128, c + 1);
        __syncthreads();
        chunk_f16<2>(HA + c * TPITCH_H, HROW_H, BsA[c & 1], wm, wn, g, r, acc);
    }
    __syncthreads();
    wbRelu(b1);

    // ---- stage 2: K = 128 ----
    ldgB(W2t, 128, 0);
    for (int c = 0; c < 4; c++) {
        stsB(BsA[c & 1]);
        if (c < 3) ldgB(W2t, 128, c + 1);
        __syncthreads();
        chunk_f16<2>(HA + c * TPITCH_H, HROW_H, BsA[c & 1], wm, wn, g, r, acc);
    }
    __syncthreads();

    // ---- epilogue (fp32 stage, pitch 132) ----
    if (EPI == EPI_ATOMIC) {
#pragma unroll
        for (int mt = 0; mt < 2; mt++)
#pragma unroll
            for (int q = 0; q < 4; q++) {
                int row = wm + mt * 16 + g + ((q & 2) ? 8 : 0);
#pragma unroll
                for (int nt = 0; nt < 8; nt++) {
                    int col = wn + nt * 8 + 2 * r + (q & 1);
                    stage[row * 132 + col] = acc[mt][nt][q] + __ldg(b2 + col);
                }
            }
        __syncthreads();
#pragma unroll
        for (int it = 0; it < 16; it++) {
            int f4  = it * 256 + tid;
            int row = f4 >> 5;
            int c4  = f4 & 31;
            float4 v = *(float4*)(stage + row * 132 + c4 * 4);
            float* dbase = out + (size_t)s_dst[row] * 128 + c4 * 4;
            asm volatile("red.global.add.v4.f32 [%0], {%1,%2,%3,%4};"
                         :: "l"(dbase), "f"(v.x), "f"(v.y), "f"(v.z), "f"(v.w)
                         : "memory");
        }
    } else {  // EPI_LNRES: out = LN(resid + acc + b2)
#pragma unroll
        for (int mt = 0; mt < 2; mt++)
#pragma unroll
            for (int q = 0; q < 4; q++) {
                int row = wm + mt * 16 + g + ((q & 2) ? 8 : 0);
#pragma unroll
                for (int nt = 0; nt < 8; nt++) {
                    int col = wn + nt * 8 + 2 * r + (q & 1);
                    stage[row * 132 + col] = acc[mt][nt][q];
                }
            }
        __syncthreads();
        float4 gg  = *(const float4*)(lng + lane * 4);
        float4 bbn = *(const float4*)(lnb + lane * 4);
        float4 bz  = *(const float4*)(b2 + lane * 4);
        for (int rr = wid; rr < 128; rr += 8) {
            float4 res = *(const float4*)(resid + (size_t)(m0 + rr) * 128 + lane * 4);
            float4 d   = *(float4*)(stage + rr * 132 + lane * 4);
            float v0 = res.x + d.x + bz.x, v1 = res.y + d.y + bz.y;
            float v2 = res.z + d.z + bz.z, v3 = res.w + d.w + bz.w;
            float sum = v0 + v1 + v2 + v3;
#pragma unroll
            for (int off = 16; off > 0; off >>= 1)
                sum += __shfl_xor_sync(0xffffffffu, sum, off);
            float mean = sum * (1.0f / 128.0f);
            float d0 = v0 - mean, d1 = v1 - mean, d2 = v2 - mean, d3 = v3 - mean;
            float sq = d0 * d0 + d1 * d1 + d2 * d2 + d3 * d3;
#pragma unroll
            for (int off = 16; off > 0; off >>= 1)
                sq += __shfl_xor_sync(0xffffffffu, sq, off);
            float inv = rsqrtf(sq * (1.0f / 128.0f) + 1e-5f);
            float4 o;
            o.x = d0 * inv * gg.x + bbn.x;
            o.y = d1 * inv * gg.y + bbn.y;
            o.z = d2 * inv * gg.z + bbn.z;
            o.w = d3 * inv * gg.w + bbn.w;
            *(float4*)(out + (size_t)(m0 + rr) * 128 + lane * 4) = o;
        }
    }
}

// ---------------- dense GEMM (fp32 A, fp16 weights), reg-prefetched --------
template <int EPI>
__global__ void __launch_bounds__(256, 2)
gemm_tc(const float* __restrict__ A, int lda, int K,
        const __half* __restrict__ Wt, const float* __restrict__ bias,
        float* __restrict__ out, int ldo,
        const float* __restrict__ resid,
        const float* __restrict__ lng, const float* __restrict__ lnb)
{
    extern __shared__ char dyn[];
    char*   base  = (char*)(((uintptr_t)dyn + 1023) & ~(uintptr_t)1023);
    __half* AsA[2] = { (__half*)base, (__half*)(base + TILE_BYTES) };
    __half* BsA[2] = { (__half*)(base + 2 * TILE_BYTES),
                       (__half*)(base + 3 * TILE_BYTES) };
    float*  stage = (float*)base;

    const int tid  = threadIdx.x;
    const int wid  = tid >> 5;
    const int lane = tid & 31;
    const int g    = lane >> 2;
    const int r    = lane & 3;
    const int wm   = (wid & 3) * 32;
    const int wn   = (wid >> 2) * 64;
    const int m0   = blockIdx.x * 128;
    const int n0   = blockIdx.y * 128;

    float acc[2][8][4];
#pragma unroll
    for (int mt = 0; mt < 2; mt++)
#pragma unroll
        for (int nt = 0; nt < 8; nt++)
#pragma unroll
            for (int q = 0; q < 4; q++) acc[mt][nt][q] = 0.f;

    int arow[4], acol[4];
#pragma unroll
    for (int i = 0; i < 4; i++) {
        int f4 = tid + i * 256;
        arow[i] = f4 >> 3;
        acol[i] = f4 & 7;
    }
    const int brow = tid >> 2, bv4 = tid & 3;
    const int brow2 = (tid + 256) >> 2, bv42 = (tid + 256) & 3;

    float4 prefA[4];
    uint4  prefB[2];

    auto ldgA = [&](int c) {
#pragma unroll
        for (int i = 0; i < 4; i++)
            prefA[i] = *(const float4*)(A + (size_t)(m0 + arow[i]) * lda + c * 32 + acol[i] * 4);
    };
    auto stsA = [&](__half* Abuf) {
#pragma unroll
        for (int i = 0; i < 4; i++)
            put4(Abuf + arow[i] * TPITCH_H, acol[i], prefA[i]);
    };
    auto ldgB = [&](int c) {
        prefB[0] = *(const uint4*)((const char*)(Wt + (size_t)(n0 + brow)  * K + c * 32) + bv4  * 16);
        prefB[1] = *(const uint4*)((const char*)(Wt + (size_t)(n0 + brow2) * K + c * 32) + bv42 * 16);
    };
    auto stsB = [&](__half* Bbuf) {
        *(uint4*)((char*)(Bbuf + brow  * TPITCH_H) + bv4  * 16) = prefB[0];
        *(uint4*)((char*)(Bbuf + brow2 * TPITCH_H) + bv42 * 16) = prefB[1];
    };

    const int NC = K >> 5;
    ldgA(0); ldgB(0);
    for (int c = 0; c < NC; c++) {
        stsA(AsA[c & 1]);
        stsB(BsA[c & 1]);
        if (c + 1 < NC) { ldgA(c + 1); ldgB(c + 1); }
        __syncthreads();
        chunk_f16<2>(AsA[c & 1], TPITCH_H, BsA[c & 1], wm, wn, g, r, acc);
    }
    __syncthreads();

#pragma unroll
    for (int mt = 0; mt < 2; mt++) {
        int rw0 = wm + mt * 16 + g;
#pragma unroll
        for (int nt = 0; nt < 8; nt++) {
            int col = wn + nt * 8 + 2 * r;
            *(float2*)(stage + rw0 * 132 + col)       = make_float2(acc[mt][nt][0], acc[mt][nt][1]);
            *(float2*)(stage + (rw0 + 8) * 132 + col) = make_float2(acc[mt][nt][2], acc[mt][nt][3]);
        }
    }
    __syncthreads();

    if (EPI == EPI_STORE) {
        // fp16 store (P): out is __half*, ldo in halves
        __half* oh = (__half*)out;
#pragma unroll
        for (int it = 0; it < 16; it++) {
            int f4  = it * 256 + tid;
            int row = f4 >> 5;
            int c4  = f4 & 31;
            float4 v = *(float4*)(stage + row * 132 + c4 * 4);
            __half2 h0 = __floats2half2_rn(v.x, v.y);
            __half2 h1 = __floats2half2_rn(v.z, v.w);
            *(uint2*)(oh + (size_t)(m0 + row) * ldo + n0 + c4 * 4) =
                make_uint2(*(uint32_t*)&h0, *(uint32_t*)&h1);
        }
    } else if (EPI == EPI_RELU) {
#pragma unroll
        for (int it = 0; it < 16; it++) {
            int f4  = it * 256 + tid;
            int row = f4 >> 5;
            int c4  = f4 & 31;
            float4 v  = *(float4*)(stage + row * 132 + c4 * 4);
            float4 bb = *(const float4*)(bias + n0 + c4 * 4);
            v.x = fmaxf(v.x + bb.x, 0.f); v.y = fmaxf(v.y + bb.y, 0.f);
            v.z = fmaxf(v.z + bb.z, 0.f); v.w = fmaxf(v.w + bb.w, 0.f);
            *(float4*)(out + (size_t)(m0 + row) * ldo + n0 + c4 * 4) = v;
        }
    } else {  // EPI_LNRES
        float4 gg  = *(const float4*)(lng + lane * 4);
        float4 bbn = *(const float4*)(lnb + lane * 4);
        float4 bz  = *(const float4*)(bias + lane * 4);
        for (int rr = wid; rr < 128; rr += 8) {
            float4 res = *(const float4*)(resid + (size_t)(m0 + rr) * 128 + lane * 4);
            float4 d   = *(float4*)(stage + rr * 132 + lane * 4);
            float v0 = res.x + d.x + bz.x, v1 = res.y + d.y + bz.y;
            float v2 = res.z + d.z + bz.z, v3 = res.w + d.w + bz.w;
            float sum = v0 + v1 + v2 + v3;
#pragma unroll
            for (int off = 16; off > 0; off >>= 1)
                sum += __shfl_xor_sync(0xffffffffu, sum, off);
            float mean = sum * (1.0f / 128.0f);
            float d0 = v0 - mean, d1 = v1 - mean, d2 = v2 - mean, d3 = v3 - mean;
            float sq = d0 * d0 + d1 * d1 + d2 * d2 + d3 * d3;
#pragma unroll
            for (int off = 16; off > 0; off >>= 1)
                sq += __shfl_xor_sync(0xffffffffu, sq, off);
            float inv = rsqrtf(sq * (1.0f / 128.0f) + 1e-5f);
            float4 o;
            o.x = d0 * inv * gg.x + bbn.x;
            o.y = d1 * inv * gg.y + bbn.y;
            o.z = d2 * inv * gg.z + bbn.z;
            o.w = d3 * inv * gg.w + bbn.w;
            *(float4*)(out + (size_t)(m0 + rr) * 128 + lane * 4) = o;
        }
    }
}

// ---------------- standalone LayerNorm (norm0) ----------------
__global__ void ln_k(float* __restrict__ io, const float* __restrict__ add,
                     const float* __restrict__ scale,
                     const float* __restrict__ g, const float* __restrict__ b,
                     int rows)
{
    int row  = blockIdx.x * 8 + (threadIdx.x >> 5);
    int lane = threadIdx.x & 31;
    if (row >= rows) return;
    float s = scale ? scale[row] : 1.0f;

    float4 x = *(const float4*)(io  + (size_t)row * 128 + lane * 4);
    float4 a = *(const float4*)(add + (size_t)row * 128 + lane * 4);
    float v[4] = { x.x + a.x * s, x.y + a.y * s, x.z + a.z * s, x.w + a.w * s };

    float sum = v[0] + v[1] + v[2] + v[3];
#pragma unroll
    for (int off = 16; off > 0; off >>= 1) sum += __shfl_xor_sync(0xffffffffu, sum, off);
    float mean = sum * (1.0f / 128.0f);
    float sq = 0.f;
#pragma unroll
    for (int j = 0; j < 4; j++) { float d = v[j] - mean; sq += d * d; }
#pragma unroll
    for (int off = 16; off > 0; off >>= 1) sq += __shfl_xor_sync(0xffffffffu, sq, off);
    float inv = rsqrtf(sq * (1.0f / 128.0f) + 1e-5f);

    float4 gg = *(const float4*)(g + lane * 4);
    float4 bb = *(const float4*)(b + lane * 4);
    float4 o;
    o.x = (v[0] - mean) * inv * gg.x + bb.x;
    o.y = (v[1] - mean) * inv * gg.y + bb.y;
    o.z = (v[2] - mean) * inv * gg.z + bb.z;
    o.w = (v[3] - mean) * inv * gg.w + bb.w;
    *(float4*)(io + (size_t)row * 128 + lane * 4) = o;
}

// ------ ONE fused setup kernel: copies + zeros + weight fp16/permute -------
__global__ void setup_all(
    float4* __restrict__ nodes4, const float4* __restrict__ x4,
    float4* __restrict__ edge4, const float4* __restrict__ eattr4,
    float4* __restrict__ agg4, float4* __restrict__ ideg4,
    __half* __restrict__ wt,
    const float* __restrict__ mW0, const float* __restrict__ mW1,
    const float* __restrict__ mW2, const float* __restrict__ fW0,
    const float* __restrict__ fW1, const float* __restrict__ xW0,
    const float* __restrict__ xW1, const float* __restrict__ xW2)
{
    int segy = blockIdx.y;
    int tid0 = blockIdx.x * blockDim.x + threadIdx.x;
    int nthr = gridDim.x * blockDim.x;
    if (segy == 0) {
        for (int i = tid0; i < NNODES * DD / 4; i += nthr) nodes4[i] = x4[i];
    } else if (segy == 1) {
        for (int i = tid0; i < EDGES * DD / 4; i += nthr) edge4[i] = eattr4[i];
    } else if (segy == 2) {
        float4 z = make_float4(0.f, 0.f, 0.f, 0.f);
        for (int i = tid0; i < NNODES * DD / 4; i += nthr) agg4[i] = z;
    } else if (segy == 3) {
        float4 z = make_float4(0.f, 0.f, 0.f, 0.f);
        for (int i = tid0; i < NNODES / 4; i += nthr) ideg4[i] = z;
    } else {
        int seg = (segy - 4) & 7, l = (segy - 4) >> 3;
        int K, N, ofs; const float* src;
        switch (seg) {
          case 0: K=KCAT; N=DD;  ofs=0;      src=mW0 + (size_t)l*KCAT*DD; break;
          case 1: K=DD;   N=DD;  ofs=49152;  src=mW1 + (size_t)l*DD*DD;  break;
          case 2: K=DD;   N=DD;  ofs=65536;  src=mW2 + (size_t)l*DD*DD;  break;
          case 3: K=DD;   N=FFH; ofs=81920;  src=fW0 + (size_t)l*DD*FFH; break;
          case 4: K=FFH;  N=DD;  ofs=147456; src=fW1 + (size_t)l*FFH*DD; break;
          case 5: K=KCAT; N=DD;  ofs=212992; src=xW0 + (size_t)l*KCAT*DD; break;
          case 6: K=DD;   N=DD;  ofs=262144; src=xW1 + (size_t)l*DD*DD;  break;
          default:K=DD;   N=DD;  ofs=278528; src=xW2 + (size_t)l*DD*DD;  break;
        }
        __half* dst = wt + (size_t)l * WT_PER_LAYER + ofs;
        if (K == KCAT) {
            for (int i = tid0; i < 49152; i += nthr) {
                int ksrc, n;
                if (i < 32768) {
                    int row = i >> 7, t = i & 127;
                    n = row & 127;
                    int kbase = (row >> 7) ? 256 : 0;
                    ksrc = kbase + perm128(t);
                } else {
                    int j = i - 32768;
                    n = j >> 7;
                    ksrc = 128 + perm128(j & 127);
                }
                dst[i] = __float2half_rn(src[(size_t)ksrc * DD + n]);
            }
        } else {
            int total = K * N;
            for (int i = tid0; i < total; i += nthr) {
                int n = i / K, rem = i - n * K;
                int k = (rem & ~127) + perm128(rem & 127);
                dst[i] = __float2half_rn(src[(size_t)k * N + n]);
            }
        }
    }
}

// ---------------- small helpers ----------------
__global__ void zero_k(float4* __restrict__ p, int n4) {
    for (int i = blockIdx.x * blockDim.x + threadIdx.x; i < n4; i += gridDim.x * blockDim.x)
        p[i] = make_float4(0.f, 0.f, 0.f, 0.f);
}
__global__ void deg_k(const int* __restrict__ dst, float* __restrict__ deg) {
    int e = blockIdx.x * blockDim.x + threadIdx.x;
    if (e < EDGES) atomicAdd(&deg[dst[e]], 1.0f);
}
__global__ void invdeg_k(float* __restrict__ deg) {
    int i = blockIdx.x * blockDim.x + threadIdx.x;
    if (i < NNODES) deg[i] = 1.0f / fmaxf(deg[i], 1.0f);
}

// ---------------- launch ----------------
extern "C" void kernel_launch(void* const* d_in, const int* in_sizes, int n_in,
                              void* d_out, int out_size)
{
    const float* x        = (const float*)d_in[0];
    const int*   eidx     = (const int*)  d_in[1];
    const float* eattr_in = (const float*)d_in[2];
    const float* msg_W0 = (const float*)d_in[3];
    const float* msg_b0 = (const float*)d_in[4];
    const float* msg_W1 = (const float*)d_in[5];
    const float* msg_b1 = (const float*)d_in[6];
    const float* msg_W2 = (const float*)d_in[7];
    const float* msg_b2 = (const float*)d_in[8];
    const float* n0g    = (const float*)d_in[9];
    const float* n0b    = (const float*)d_in[10];
    const float* ff_W0  = (const float*)d_in[11];
    const float* ff_b0  = (const float*)d_in[12];
    const float* ff_W1  = (const float*)d_in[13];
    const float* ff_b1  = (const float*)d_in[14];
    const float* n1g    = (const float*)d_in[15];
    const float* n1b    = (const float*)d_in[16];
    const float* eW0    = (const float*)d_in[17];
    const float* eb0    = (const float*)d_in[18];
    const float* eW1    = (const float*)d_in[19];
    const float* eb1    = (const float*)d_in[20];
    const float* eW2    = (const float*)d_in[21];
    const float* eb2    = (const float*)d_in[22];
    const float* eng    = (const float*)d_in[23];
    const float* enb    = (const float*)d_in[24];

    float* nodes = (float*)d_out;
    const int* src = eidx;
    const int* dst = eidx + EDGES;

    static bool init = false;
    static float *edge, *agg, *ffb, *ideg;
    static __half *P, *wt;
    if (!init) {
        cudaGetSymbolAddress((void**)&edge, g_edge);
        cudaGetSymbolAddress((void**)&agg,  g_agg);
        cudaGetSymbolAddress((void**)&ffb,  g_ff);
        cudaGetSymbolAddress((void**)&ideg, g_ideg);
        cudaGetSymbolAddress((void**)&P,    g_P);
        cudaGetSymbolAddress((void**)&wt,   g_wt);
        cudaFuncSetAttribute(mlp3_tc<EPI_ATOMIC>,
                             cudaFuncAttributeMaxDynamicSharedMemorySize, DYN_MLP);
        cudaFuncSetAttribute(mlp3_tc<EPI_LNRES>,
                             cudaFuncAttributeMaxDynamicSharedMemorySize, DYN_MLP);
        cudaFuncSetAttribute(gemm_tc<EPI_RELU>,
                             cudaFuncAttributeMaxDynamicSharedMemorySize, DYN_GEMM);
        cudaFuncSetAttribute(gemm_tc<EPI_LNRES>,
                             cudaFuncAttributeMaxDynamicSharedMemorySize, DYN_GEMM);
        cudaFuncSetAttribute(gemm_tc<EPI_STORE>,
                             cudaFuncAttributeMaxDynamicSharedMemorySize, DYN_GEMM);
        init = true;
    }

    setup_all<<<dim3(256, 20), 256>>>(
        (float4*)nodes, (const float4*)x, (float4*)edge, (const float4*)eattr_in,
        (float4*)agg, (float4*)ideg, wt,
        msg_W0, msg_W1, msg_W2, ff_W0, ff_W1, eW0, eW1, eW2);
    deg_k<<<EDGES / 256, 256>>>(dst, ideg);
    invdeg_k<<<NNODES / 256, 256>>>(ideg);

    const dim3 gE(EDGES / 128, 1), gN(NNODES / 128, 1), gF(NNODES / 128, FFH / 128);
    const dim3 gP(NNODES / 128, 2);

    for (int l = 0; l < LAYERS; l++) {
        __half* wl = wt + (size_t)l * WT_PER_LAYER;
        const int O_MW0 = 0, O_MW1 = 49152, O_MW2 = 65536, O_FW0 = 81920,
                  O_FW1 = 147456, O_EW0 = 212992, O_EW1 = 262144, O_EW2 = 278528;

        if (l > 0) zero_k<<<4096, 256>>>((float4*)agg, NNODES * DD / 4);

        // P = nodes @ [W0a | W0c] (fp16) for the message MLP
        gemm_tc<EPI_STORE><<<gP, 256, DYN_GEMM>>>(
            nodes, DD, DD, wl + O_MW0, nullptr, (float*)P, 256,
            nullptr, nullptr, nullptr);
        mlp3_tc<EPI_ATOMIC><<<gE, 256, DYN_MLP>>>(
            edge, src, dst, P,
            wl + O_MW0 + 32768, msg_b0 + l * DD,
            wl + O_MW1, msg_b1 + l * DD,
            wl + O_MW2, msg_b2 + l * DD,
            agg, nullptr, nullptr, nullptr);
        ln_k<<<NNODES / 8, 256>>>(nodes, agg, ideg, n0g + l * DD, n0b + l * DD, NNODES);

        gemm_tc<EPI_RELU><<<gF, 256, DYN_GEMM>>>(
            nodes, DD, DD, wl + O_FW0, ff_b0 + l * FFH, ffb, FFH,
            nullptr, nullptr, nullptr);
        gemm_tc<EPI_LNRES><<<gN, 256, DYN_GEMM>>>(
            ffb, FFH, FFH, wl + O_FW1, ff_b1 + l * DD, nodes, DD,
            nodes, n1g + l * DD, n1b + l * DD);

        // P = nodes @ [eW0a | eW0c] (fp16) for the edge MLP
        gemm_tc<EPI_STORE><<<gP, 256, DYN_GEMM>>>(
            nodes, DD, DD, wl + O_EW0, nullptr, (float*)P, 256,
            nullptr, nullptr, nullptr);
        mlp3_tc<EPI_LNRES><<<gE, 256, DYN_MLP>>>(
            edge, src, dst, P,
            wl + O_EW0 + 32768, eb0 + l * DD,
            wl + O_EW1, eb1 + l * DD,
            wl + O_EW2, eb2 + l * DD,
            edge, edge, eng + l * DD, enb + l * DD);
    }
    // nodes (= d_out) holds the final [B, N, D] result.
}